// round 8
// baseline (speedup 1.0000x reference)
#include <cuda_runtime.h>

// out[b,p,:] = { c1*c2*c3, c0*c1, c0*c1*c2, c0*c1*c2*c3 }, c_i = cos(patches[b,p,i]).
// RZ params provably do not affect the output (unit phases cancel in |amp|^2).
//
// R8: finest dispatch granularity at full coverage: 4096 CTAs x 64 threads
// (1 warp/CTA-pair scheduling quantum), one 256-bit ld + one 256-bit st per
// thread (2 patches/thread), MUFU cosine. Minimal per-thread stream:
// LDG.256 + 8 MUFU + 7 FMUL + STG.256.

#define TPB 64

__global__ __launch_bounds__(TPB) void quantum_patch_kernel(
    const float* __restrict__ in,
    float* __restrict__ out) {
    size_t t = (size_t)blockIdx.x * TPB + threadIdx.x;
    const float* ip = in + t * 8;
    float* op = out + t * 8;

    float x[8];
    asm("ld.global.nc.v8.f32 {%0,%1,%2,%3,%4,%5,%6,%7}, [%8];"
        : "=f"(x[0]), "=f"(x[1]), "=f"(x[2]), "=f"(x[3]),
          "=f"(x[4]), "=f"(x[5]), "=f"(x[6]), "=f"(x[7])
        : "l"(ip));

    float o[8];
    #pragma unroll
    for (int p = 0; p < 2; p++) {
        float c0 = __cosf(x[4 * p + 0]);
        float c1 = __cosf(x[4 * p + 1]);
        float c2 = __cosf(x[4 * p + 2]);
        float c3 = __cosf(x[4 * p + 3]);
        float c12  = c1 * c2;
        float c123 = c12 * c3;
        o[4 * p + 0] = c123;
        o[4 * p + 1] = c0 * c1;
        o[4 * p + 2] = c0 * c12;
        o[4 * p + 3] = c0 * c123;
    }

    asm volatile("st.global.v8.f32 [%0], {%1,%2,%3,%4,%5,%6,%7,%8};"
        :: "l"(op),
           "f"(o[0]), "f"(o[1]), "f"(o[2]), "f"(o[3]),
           "f"(o[4]), "f"(o[5]), "f"(o[6]), "f"(o[7])
        : "memory");
}

// Fallback (float4, guarded) for non-multiple sizes.
__global__ __launch_bounds__(256) void quantum_patch_kernel_guarded(
    const float4* __restrict__ in,
    float4* __restrict__ out,
    int n_patches) {
    int i = blockIdx.x * 256 + threadIdx.x;
    if (i < n_patches) {
        float4 x = in[i];
        float c0 = __cosf(x.x), c1 = __cosf(x.y), c2 = __cosf(x.z), c3 = __cosf(x.w);
        float c12 = c1 * c2;
        float c123 = c12 * c3;
        float4 o;
        o.x = c123;
        o.y = c0 * c1;
        o.z = c0 * c12;
        o.w = c0 * c123;
        out[i] = o;
    }
}

extern "C" void kernel_launch(void* const* d_in, const int* in_sizes, int n_in,
                              void* d_out, int out_size) {
    const float* patches = (const float*)d_in[0];     // (256, 2048, 4) f32
    float* out = (float*)d_out;                       // (256, 8192) f32 — same layout
    int n_patches = in_sizes[0] / 4;                  // 524288
    const int patches_per_block = TPB * 2;            // 128 (2 patches/thread)
    if (n_patches % patches_per_block == 0) {
        quantum_patch_kernel<<<n_patches / patches_per_block, TPB>>>(patches, out);  // 4096 CTAs
    } else {
        quantum_patch_kernel_guarded<<<(n_patches + 255) / 256, 256>>>(
            (const float4*)patches, (float4*)out, n_patches);
    }
}

// round 9
// speedup vs baseline: 1.3413x; 1.3413x over previous
#include <cuda_runtime.h>

// out[b,p,:] = { c1*c2*c3, c0*c1, c0*c1*c2, c0*c1*c2*c3 }, c_i = cos(patches[b,p,i]).
// RZ params provably do not affect the output (unit phases cancel in |amp|^2).
//
// R9 (final): best-measured configuration from the 8-round search:
//   - 1024 CTAs x 256 threads (single wave, optimal CTA granularity;
//     64-thr and 1024-thr CTAs both regressed, 512-2048 CTA count flat)
//   - 2 patches/thread as two strided float4 ld/st (best cold-cache ncu
//     duration, 5.70us)
//   - MUFU cosine (minimal issue count; FMA-poly variant proved the kernel
//     is not MUFU-bound, so MUFU is free and shortest)
// Kernel is at a burst-latency floor (~5.7us cold / 6.6us timed); all pipes
// <= 35% across every tested variant.

#define ITEMS 2
#define TPB   256

__device__ __forceinline__ float4 qpatch(float4 x) {
    float c0 = __cosf(x.x);
    float c1 = __cosf(x.y);
    float c2 = __cosf(x.z);
    float c3 = __cosf(x.w);
    float c12  = c1 * c2;
    float c123 = c12 * c3;
    float4 o;
    o.x = c123;
    o.y = c0 * c1;
    o.z = c0 * c12;
    o.w = c0 * c123;
    return o;
}

__global__ __launch_bounds__(TPB) void quantum_patch_kernel(
    const float4* __restrict__ in,
    float4* __restrict__ out) {
    int base = blockIdx.x * (TPB * ITEMS) + threadIdx.x;

    // Front-batched independent non-coherent loads.
    float4 x0 = __ldg(in + base);
    float4 x1 = __ldg(in + base + TPB);

    out[base]       = qpatch(x0);
    out[base + TPB] = qpatch(x1);
}

// Fallback (guarded) for non-multiple sizes.
__global__ __launch_bounds__(TPB) void quantum_patch_kernel_guarded(
    const float4* __restrict__ in,
    float4* __restrict__ out,
    int n_patches) {
    int i = blockIdx.x * TPB + threadIdx.x;
    if (i < n_patches) out[i] = qpatch(__ldg(in + i));
}

extern "C" void kernel_launch(void* const* d_in, const int* in_sizes, int n_in,
                              void* d_out, int out_size) {
    const float4* patches = (const float4*)d_in[0];   // (256, 2048, 4) f32
    float4* out = (float4*)d_out;                     // (256, 8192) f32 — same layout
    int n_patches = in_sizes[0] / 4;                  // 524288
    const int per_block = TPB * ITEMS;                // 512
    if (n_patches % per_block == 0) {
        quantum_patch_kernel<<<n_patches / per_block, TPB>>>(patches, out);  // 1024 CTAs
    } else {
        quantum_patch_kernel_guarded<<<(n_patches + TPB - 1) / TPB, TPB>>>(patches, out, n_patches);
    }
}

// round 10
// speedup vs baseline: 1.3478x; 1.0048x over previous
#include <cuda_runtime.h>

// out[b,p,:] = { c1*c2*c3, c0*c1, c0*c1*c2, c0*c1*c2*c3 }, c_i = cos(patches[b,p,i]).
// RZ params provably do not affect the output (unit phases cancel in |amp|^2).
//
// R10 (converged): 9-round search established a burst-latency floor
// (~5.7us ncu-cold / ~6.63us timed) invariant to ILP, vector width, math
// pipe, and launch geometry within the good range. This is the minimal
// per-thread instruction stream at the optimal granularity:
//   1024 CTAs x 256 threads, 2 patches/thread via one 256-bit ld.global.nc
//   + 8 MUFU.COS + 7 FMUL + one 256-bit st.global.
// Regressions mapped: 64-thr CTAs (+2.3us), 1024-thr CTAs (+0.65us);
// everything else ties within timer noise (~32ns).

#define TPB 256

__global__ __launch_bounds__(TPB) void quantum_patch_kernel(
    const float* __restrict__ in,
    float* __restrict__ out) {
    size_t t = (size_t)blockIdx.x * TPB + threadIdx.x;
    const float* ip = in + t * 8;
    float* op = out + t * 8;

    float x[8];
    asm("ld.global.nc.v8.f32 {%0,%1,%2,%3,%4,%5,%6,%7}, [%8];"
        : "=f"(x[0]), "=f"(x[1]), "=f"(x[2]), "=f"(x[3]),
          "=f"(x[4]), "=f"(x[5]), "=f"(x[6]), "=f"(x[7])
        : "l"(ip));

    float o[8];
    #pragma unroll
    for (int p = 0; p < 2; p++) {
        float c0 = __cosf(x[4 * p + 0]);
        float c1 = __cosf(x[4 * p + 1]);
        float c2 = __cosf(x[4 * p + 2]);
        float c3 = __cosf(x[4 * p + 3]);
        float c12  = c1 * c2;
        float c123 = c12 * c3;
        o[4 * p + 0] = c123;
        o[4 * p + 1] = c0 * c1;
        o[4 * p + 2] = c0 * c12;
        o[4 * p + 3] = c0 * c123;
    }

    asm volatile("st.global.v8.f32 [%0], {%1,%2,%3,%4,%5,%6,%7,%8};"
        :: "l"(op),
           "f"(o[0]), "f"(o[1]), "f"(o[2]), "f"(o[3]),
           "f"(o[4]), "f"(o[5]), "f"(o[6]), "f"(o[7])
        : "memory");
}

// Fallback (float4, guarded) for non-multiple sizes.
__global__ __launch_bounds__(TPB) void quantum_patch_kernel_guarded(
    const float4* __restrict__ in,
    float4* __restrict__ out,
    int n_patches) {
    int i = blockIdx.x * TPB + threadIdx.x;
    if (i < n_patches) {
        float4 x = in[i];
        float c0 = __cosf(x.x), c1 = __cosf(x.y), c2 = __cosf(x.z), c3 = __cosf(x.w);
        float c12 = c1 * c2;
        float c123 = c12 * c3;
        float4 o;
        o.x = c123;
        o.y = c0 * c1;
        o.z = c0 * c12;
        o.w = c0 * c123;
        out[i] = o;
    }
}

extern "C" void kernel_launch(void* const* d_in, const int* in_sizes, int n_in,
                              void* d_out, int out_size) {
    const float* patches = (const float*)d_in[0];     // (256, 2048, 4) f32
    float* out = (float*)d_out;                       // (256, 8192) f32 — same layout
    int n_patches = in_sizes[0] / 4;                  // 524288
    const int patches_per_block = TPB * 2;            // 512 (2 patches/thread)
    if (n_patches % patches_per_block == 0) {
        quantum_patch_kernel<<<n_patches / patches_per_block, TPB>>>(patches, out);  // 1024 CTAs
    } else {
        quantum_patch_kernel_guarded<<<(n_patches + TPB - 1) / TPB, TPB>>>(
            (const float4*)patches, (float4*)out, n_patches);
    }
}